// round 9
// baseline (speedup 1.0000x reference)
#include <cuda_runtime.h>

#define N_BINS 85
#define NBLOCKS 592             // 4 CTAs/SM * 148 SMs
#define GROUPS_PER_BLOCK 3
#define ACTIVE_THREADS (GROUPS_PER_BLOCK * N_BINS)   // 255
#define BLOCK_THREADS 256
#define TOTAL_GROUPS (NBLOCKS * GROUPS_PER_BLOCK)    // 1776

// Globals (zero at module load; last block resets via atomicExch each call,
// so graph replays are deterministic). No dynamic allocation.
__device__ float g_acc[N_BINS];
__device__ unsigned int g_count;

// ---------------------------------------------------------------------------
// Single fused kernel. 4 CTAs/SM -> 64 registers/thread: ptxas can keep
// ~12-14 LDG.128 in flight per warp (vs ~3 at the old 32-reg budget),
// raising MLP_eff, which the 3-term LDG model says gates cyc/LDG.
// Mainloop: grid-stride over super-rows (4 rows = 85 float4s), unroll 8.
// Epilogue: one fence per block + ticket; last block finishes (cheap, proven).
// ---------------------------------------------------------------------------
__global__ void __launch_bounds__(BLOCK_THREADS, 4)
emd_fused(const float4* __restrict__ in4, const float4* __restrict__ tg4,
          const float* __restrict__ in, const float* __restrict__ tg,
          int nsuper, int total_elems, float* __restrict__ out)
{
    __shared__ float sd[N_BINS];
    __shared__ int islast;
    int t = threadIdx.x;
    if (t < N_BINS) sd[t] = 0.0f;

    float a0 = 0.f, a1 = 0.f, a2 = 0.f, a3 = 0.f;
    int p = 0;
    if (t < ACTIVE_THREADS) {
        int g = blockIdx.x * GROUPS_PER_BLOCK + (t / N_BINS);
        p = t % N_BINS;
        #pragma unroll 8
        for (int s = g; s < nsuper; s += TOTAL_GROUPS) {
            int idx = s * N_BINS + p;          // float4 index; ~10.6M max, fits int
            float4 a = in4[idx];
            float4 b = tg4[idx];
            a0 += a.x - b.x;
            a1 += a.y - b.y;
            a2 += a.z - b.z;
            a3 += a.w - b.w;
        }
    }
    __syncthreads();
    if (t < ACTIVE_THREADS) {
        atomicAdd(&sd[(4 * p) % N_BINS],     a0);
        atomicAdd(&sd[(4 * p + 1) % N_BINS], a1);
        atomicAdd(&sd[(4 * p + 2) % N_BINS], a2);
        atomicAdd(&sd[(4 * p + 3) % N_BINS], a3);
    }
    // Tail rows (B % 4 != 0): scalar, block 0 only. (B=500000 -> empty loop.)
    if (blockIdx.x == 0) {
        int tail_start = nsuper * (4 * N_BINS);
        for (int i = tail_start + t; i < total_elems; i += BLOCK_THREADS) {
            atomicAdd(&sd[i % N_BINS], in[i] - tg[i]);
        }
    }
    __syncthreads();

    // Publish block partials via L2 float atomics (85 distinct addresses).
    if (t < N_BINS) atomicAdd(&g_acc[t], sd[t]);
    __syncthreads();          // publishers' atomics visible to t0 (block scope)
    if (t == 0) {
        __threadfence();      // ONE cumulative release fence per block
        unsigned int ticket = atomicAdd(&g_count, 1u);
        islast = (ticket == NBLOCKS - 1u);
    }
    __syncthreads();

    if (islast) {
        __shared__ float d[N_BINS];
        if (t == 0) __threadfence();           // acquire side
        __syncthreads();
        if (t < N_BINS) {
            // L2-coherent read + reset in one atomic; no L1 staleness possible.
            float v = atomicExch(&g_acc[t], 0.0f);
            d[t] = fabsf(v);
        }
        __syncthreads();
        if (t == 0) {
            float cum = 0.f, loss = 0.f;
            #pragma unroll
            for (int j = 0; j < N_BINS; j++) {
                cum += d[j];
                loss += cum / (float)(j + 1);
            }
            out[0] = loss * 0.1f;
            atomicExch(&g_count, 0u);          // reset ticket for next replay
        }
    }
}

extern "C" void kernel_launch(void* const* d_in, const int* in_sizes, int n_in,
                              void* d_out, int out_size)
{
    const float* in = (const float*)d_in[0];
    const float* tg = (const float*)d_in[1];
    int total = in_sizes[0];            // 500000 * 85
    int B = total / N_BINS;
    int nsuper = B / 4;

    emd_fused<<<NBLOCKS, BLOCK_THREADS>>>((const float4*)in, (const float4*)tg,
                                          in, tg, nsuper, total, (float*)d_out);
}